// round 1
// baseline (speedup 1.0000x reference)
#include <cuda_runtime.h>
#include <cstdint>

#define NNODES 1024
#define NIN    256
#define HIDEND 768      // NNODES - NOUT
#define NOUT   256
#define BATCH  8192
#define MAXP   128      // padded nnz capacity per row (mean ~38, 128 is >10 sigma)
#define ZSTR   33       // padded stride for z[node][lane] in smem

// ---- device-global scratch (static module memory: allowed) ----
__device__ int2 g_pairs[NNODES * MAXP];   // (col*ZSTR, bits(w)) per nonzero
__device__ int  g_counts[NNODES];

// ============================================================================
// Kernel 1: build padded CSR of W on device (runs every launch, deterministic)
// one warp per row; ballot-based compaction; order deterministic.
// ============================================================================
__global__ void build_csr_kernel(const float* __restrict__ W)
{
    int row  = blockIdx.x;
    int lane = threadIdx.x;
    const float4* wr = reinterpret_cast<const float4*>(W + (size_t)row * NNODES);
    int cnt = 0;
    #pragma unroll
    for (int c4 = 0; c4 < NNODES / 4; c4 += 32) {
        float4 v = wr[c4 + lane];
        int bc = (c4 + lane) * 4;
        #pragma unroll
        for (int q = 0; q < 4; ++q) {
            float w = (q == 0) ? v.x : (q == 1) ? v.y : (q == 2) ? v.z : v.w;
            unsigned m = __ballot_sync(0xffffffffu, w != 0.0f);
            if (w != 0.0f) {
                int pos = cnt + __popc(m & ((1u << lane) - 1u));
                if (pos < MAXP)
                    g_pairs[row * MAXP + pos] = make_int2((bc + q) * ZSTR,
                                                          __float_as_int(w));
            }
            cnt += __popc(m);
        }
    }
    if (lane == 0) g_counts[row] = (cnt < MAXP) ? cnt : MAXP;
}

// ============================================================================
// Kernel 2: main DAG propagation.
// Block = 64 threads = 2 independent warps; each warp owns 32 batch elements.
// Per-warp smem: z[768][32] (stride 33), 32x32 output staging, 4-deep ring
// buffer of prefetched (col,w) rows. No cross-warp sync in the hot loop.
// ============================================================================
extern __shared__ float smem[];

__global__ void __launch_bounds__(64, 1)
dagnn_main(const float* __restrict__ x,
           const float* __restrict__ b,
           float* __restrict__ out)
{
    const int ZF    = HIDEND * ZSTR;   // 25344 floats per warp
    const int STF   = 32 * ZSTR;       // 1056 floats per warp
    const int RINGF = 4 * MAXP * 2;    // 4 slots * 128 pairs * 2 words

    float* zbase    = smem;
    float* stbase   = smem + 2 * ZF;
    float* ringbase = stbase + 2 * STF;
    float* bsh      = ringbase + 2 * RINGF;
    int*   csh      = reinterpret_cast<int*>(bsh + NNODES);

    int tid  = threadIdx.x;
    int wid  = tid >> 5;
    int lane = tid & 31;

    // cooperative load of bias + counts into smem
    for (int t = tid; t < NNODES; t += 64) {
        bsh[t] = b[t];
        csh[t] = g_counts[t];
    }
    __syncthreads();

    float* zw   = zbase + wid * ZF;
    float* zl   = zw + lane;                       // this lane's batch column
    float* stg  = stbase + wid * STF;
    int2*  ring = reinterpret_cast<int2*>(ringbase + wid * RINGF);

    int b0 = (blockIdx.x * 2 + wid) * 32;          // batch base for this warp

    // ---- transpose x[b0..b0+31][0..255] into z[node][lane] (coalesced) ----
    for (int t = lane; t < NIN * 32; t += 32) {
        int n = t & (NIN - 1);
        int r = t >> 8;
        zw[n * ZSTR + r] = x[(size_t)(b0 + r) * NIN + n];
    }
    __syncwarp();

    // ---- prologue: stage rows 256,257 into ring slots 0,1 ----
    for (int s = 0; s < 2; ++s) {
        int r = NIN + s;
        int cn = csh[r];
        const int2* src = g_pairs + r * MAXP;
        int2* dst = ring + s * MAXP;
        for (int t = lane; t < cn; t += 32) dst[t] = src[t];
    }
    // P = row 258 (to be STS'd at iter 256), A = row 259
    int2 P0 = {0,0}, P1 = {0,0}, P2 = {0,0}, P3 = {0,0};
    int2 A0 = {0,0}, A1 = {0,0}, A2 = {0,0}, A3 = {0,0};
    {
        int r = NIN + 2; int c = csh[r];
        const int2* s = g_pairs + r * MAXP;
        if (lane      < c) P0 = s[lane];
        if (lane + 32 < c) P1 = s[lane + 32];
        if (lane + 64 < c) P2 = s[lane + 64];
        if (lane + 96 < c) P3 = s[lane + 96];
    }
    {
        int r = NIN + 3; int c = csh[r];
        const int2* s = g_pairs + r * MAXP;
        if (lane      < c) A0 = s[lane];
        if (lane + 32 < c) A1 = s[lane + 32];
        if (lane + 64 < c) A2 = s[lane + 64];
        if (lane + 96 < c) A3 = s[lane + 96];
    }

    int sl = 0;
    for (int i = NIN; i < NNODES; ++i) {
        __syncwarp();

        // STS P (row i+2, LDG'd 2 iters ago -> L2 latency covered)
        int ip2 = i + 2;
        if (ip2 < NNODES) {
            int cb = csh[ip2];
            int2* dst = ring + ((sl + 2) & 3) * MAXP;
            if (lane      < cb) dst[lane]      = P0;
            if (lane + 32 < cb) dst[lane + 32] = P1;
            if (lane + 64 < cb) dst[lane + 64] = P2;
            if (lane + 96 < cb) dst[lane + 96] = P3;
        }
        // rotate and issue LDG for row i+4
        P0 = A0; P1 = A1; P2 = A2; P3 = A3;
        int ip4 = i + 4;
        if (ip4 < NNODES) {
            int ca = csh[ip4];
            const int2* src = g_pairs + ip4 * MAXP;
            if (lane      < ca) A0 = src[lane];
            if (lane + 32 < ca) A1 = src[lane + 32];
            if (lane + 64 < ca) A2 = src[lane + 64];
            if (lane + 96 < ca) A3 = src[lane + 96];
        }

        // ---- consume row i from ring slot sl ----
        int cnt = csh[i];
        const int2* pb = ring + sl * MAXP;
        float a0 = bsh[i], a1 = 0.f, a2 = 0.f, a3 = 0.f;
        int k = 0;
        for (; k + 4 <= cnt; k += 4) {
            int2 q0 = pb[k], q1 = pb[k + 1], q2 = pb[k + 2], q3 = pb[k + 3];
            a0 = fmaf(__int_as_float(q0.y), zl[q0.x], a0);
            a1 = fmaf(__int_as_float(q1.y), zl[q1.x], a1);
            a2 = fmaf(__int_as_float(q2.y), zl[q2.x], a2);
            a3 = fmaf(__int_as_float(q3.y), zl[q3.x], a3);
        }
        for (; k < cnt; ++k) {
            int2 q = pb[k];
            a0 = fmaf(__int_as_float(q.y), zl[q.x], a0);
        }
        float a = (a0 + a1) + (a2 + a3);

        if (i < HIDEND) {
            // tanh(a) = 1 - 2/(exp(2a)+1); saturates correctly at +/-inf
            float e = __expf(a + a);
            zl[i * ZSTR] = 1.0f - __fdividef(2.0f, e + 1.0f);
        } else {
            int c = (i - HIDEND) & 31;
            stg[c * ZSTR + lane] = a;          // stage[node][batch]
            if (c == 31) {
                __syncwarp();
                int g = ((i - HIDEND) >> 5) << 5;
                #pragma unroll 4
                for (int m = 0; m < 32; ++m) {
                    // lane -> output column (coalesced 128B), conflict-free LDS
                    out[(size_t)(b0 + m) * NOUT + g + lane] = stg[lane * ZSTR + m];
                }
                __syncwarp();
            }
        }
        sl = (sl + 1) & 3;
    }
}

// ============================================================================
extern "C" void kernel_launch(void* const* d_in, const int* in_sizes, int n_in,
                              void* d_out, int out_size)
{
    const float* x = nullptr;
    const float* W = nullptr;
    const float* b = nullptr;
    for (int i = 0; i < n_in; ++i) {
        if      (in_sizes[i] == BATCH * NIN)     x = (const float*)d_in[i];
        else if (in_sizes[i] == NNODES * NNODES) W = (const float*)d_in[i];
        else if (in_sizes[i] == NNODES)          b = (const float*)d_in[i];
    }

    build_csr_kernel<<<NNODES, 32>>>(W);

    int smem_bytes = (2 * HIDEND * ZSTR      // z
                    + 2 * 32 * ZSTR          // output staging
                    + 2 * 4 * MAXP * 2       // ring buffers
                    + NNODES) * (int)sizeof(float)
                    + NNODES * (int)sizeof(int);   // = 227,584 B
    cudaFuncSetAttribute(dagnn_main,
                         cudaFuncAttributeMaxDynamicSharedMemorySize, smem_bytes);

    dagnn_main<<<BATCH / 64, 64, smem_bytes>>>(x, b, (float*)d_out);
}

// round 2
// speedup vs baseline: 1.0043x; 1.0043x over previous
#include <cuda_runtime.h>
#include <cstdint>

#define NNODES 1024
#define NIN    256
#define HIDEND 768      // NNODES - NOUT
#define NOUT   256
#define BATCH  8192
#define MAXP   128      // padded nnz capacity per row (mean ~38, 128 is >10 sigma)
#define ZSTR   33       // padded stride for z[node][lane] in smem

// ---- device-global scratch (static module memory: allowed) ----
__device__ int2 g_pairs[NNODES * MAXP];   // (col*ZSTR, bits(w)) per nonzero
__device__ int  g_counts[NNODES];

// ============================================================================
// Kernel 1: build padded CSR of W on device (runs every launch, deterministic)
// one warp per row; ballot-based compaction; order deterministic.
// ============================================================================
__global__ void build_csr_kernel(const float* __restrict__ W)
{
    int row  = blockIdx.x;
    int lane = threadIdx.x;
    const float4* wr = reinterpret_cast<const float4*>(W + (size_t)row * NNODES);
    int cnt = 0;
    #pragma unroll
    for (int c4 = 0; c4 < NNODES / 4; c4 += 32) {
        float4 v = wr[c4 + lane];
        int bc = (c4 + lane) * 4;
        #pragma unroll
        for (int q = 0; q < 4; ++q) {
            float w = (q == 0) ? v.x : (q == 1) ? v.y : (q == 2) ? v.z : v.w;
            unsigned m = __ballot_sync(0xffffffffu, w != 0.0f);
            if (w != 0.0f) {
                int pos = cnt + __popc(m & ((1u << lane) - 1u));
                if (pos < MAXP)
                    g_pairs[row * MAXP + pos] = make_int2((bc + q) * ZSTR,
                                                          __float_as_int(w));
            }
            cnt += __popc(m);
        }
    }
    if (lane == 0) g_counts[row] = (cnt < MAXP) ? cnt : MAXP;
}

// ============================================================================
// Kernel 2: main DAG propagation.
// Block = 64 threads = 2 independent warps; each warp owns 32 batch elements.
// Per-warp smem: z[768][32] (stride 33), 32x32 output staging, 4-deep ring
// buffer of prefetched (col,w) rows. No cross-warp sync in the hot loop.
// ============================================================================
extern __shared__ float smem[];

__global__ void __launch_bounds__(64, 1)
dagnn_main(const float* __restrict__ x,
           const float* __restrict__ b,
           float* __restrict__ out)
{
    const int ZF    = HIDEND * ZSTR;   // 25344 floats per warp
    const int STF   = 32 * ZSTR;       // 1056 floats per warp
    const int RINGF = 4 * MAXP * 2;    // 4 slots * 128 pairs * 2 words

    float* zbase    = smem;
    float* stbase   = smem + 2 * ZF;
    float* ringbase = stbase + 2 * STF;
    float* bsh      = ringbase + 2 * RINGF;
    int*   csh      = reinterpret_cast<int*>(bsh + NNODES);

    int tid  = threadIdx.x;
    int wid  = tid >> 5;
    int lane = tid & 31;

    // cooperative load of bias + counts into smem
    for (int t = tid; t < NNODES; t += 64) {
        bsh[t] = b[t];
        csh[t] = g_counts[t];
    }
    __syncthreads();

    float* zw   = zbase + wid * ZF;
    float* zl   = zw + lane;                       // this lane's batch column
    float* stg  = stbase + wid * STF;
    int2*  ring = reinterpret_cast<int2*>(ringbase + wid * RINGF);

    int b0 = (blockIdx.x * 2 + wid) * 32;          // batch base for this warp

    // ---- transpose x[b0..b0+31][0..255] into z[node][lane] (coalesced) ----
    for (int t = lane; t < NIN * 32; t += 32) {
        int n = t & (NIN - 1);
        int r = t >> 8;
        zw[n * ZSTR + r] = x[(size_t)(b0 + r) * NIN + n];
    }
    __syncwarp();

    // ---- prologue: stage rows 256,257 into ring slots 0,1 ----
    for (int s = 0; s < 2; ++s) {
        int r = NIN + s;
        int cn = csh[r];
        const int2* src = g_pairs + r * MAXP;
        int2* dst = ring + s * MAXP;
        for (int t = lane; t < cn; t += 32) dst[t] = src[t];
    }
    // P = row 258 (to be STS'd at iter 256), A = row 259
    int2 P0 = {0,0}, P1 = {0,0}, P2 = {0,0}, P3 = {0,0};
    int2 A0 = {0,0}, A1 = {0,0}, A2 = {0,0}, A3 = {0,0};
    {
        int r = NIN + 2; int c = csh[r];
        const int2* s = g_pairs + r * MAXP;
        if (lane      < c) P0 = s[lane];
        if (lane + 32 < c) P1 = s[lane + 32];
        if (lane + 64 < c) P2 = s[lane + 64];
        if (lane + 96 < c) P3 = s[lane + 96];
    }
    {
        int r = NIN + 3; int c = csh[r];
        const int2* s = g_pairs + r * MAXP;
        if (lane      < c) A0 = s[lane];
        if (lane + 32 < c) A1 = s[lane + 32];
        if (lane + 64 < c) A2 = s[lane + 64];
        if (lane + 96 < c) A3 = s[lane + 96];
    }

    int sl = 0;
    for (int i = NIN; i < NNODES; ++i) {
        __syncwarp();

        // STS P (row i+2, LDG'd 2 iters ago -> L2 latency covered)
        int ip2 = i + 2;
        if (ip2 < NNODES) {
            int cb = csh[ip2];
            int2* dst = ring + ((sl + 2) & 3) * MAXP;
            if (lane      < cb) dst[lane]      = P0;
            if (lane + 32 < cb) dst[lane + 32] = P1;
            if (lane + 64 < cb) dst[lane + 64] = P2;
            if (lane + 96 < cb) dst[lane + 96] = P3;
        }
        // rotate and issue LDG for row i+4
        P0 = A0; P1 = A1; P2 = A2; P3 = A3;
        int ip4 = i + 4;
        if (ip4 < NNODES) {
            int ca = csh[ip4];
            const int2* src = g_pairs + ip4 * MAXP;
            if (lane      < ca) A0 = src[lane];
            if (lane + 32 < ca) A1 = src[lane + 32];
            if (lane + 64 < ca) A2 = src[lane + 64];
            if (lane + 96 < ca) A3 = src[lane + 96];
        }

        // ---- consume row i from ring slot sl ----
        int cnt = csh[i];
        const int2* pb = ring + sl * MAXP;
        float a0 = bsh[i], a1 = 0.f, a2 = 0.f, a3 = 0.f;
        int k = 0;
        for (; k + 4 <= cnt; k += 4) {
            int2 q0 = pb[k], q1 = pb[k + 1], q2 = pb[k + 2], q3 = pb[k + 3];
            a0 = fmaf(__int_as_float(q0.y), zl[q0.x], a0);
            a1 = fmaf(__int_as_float(q1.y), zl[q1.x], a1);
            a2 = fmaf(__int_as_float(q2.y), zl[q2.x], a2);
            a3 = fmaf(__int_as_float(q3.y), zl[q3.x], a3);
        }
        for (; k < cnt; ++k) {
            int2 q = pb[k];
            a0 = fmaf(__int_as_float(q.y), zl[q.x], a0);
        }
        float a = (a0 + a1) + (a2 + a3);

        if (i < HIDEND) {
            // tanh(a) = 1 - 2/(exp(2a)+1); saturates correctly at +/-inf
            float e = __expf(a + a);
            zl[i * ZSTR] = 1.0f - __fdividef(2.0f, e + 1.0f);
        } else {
            int c = (i - HIDEND) & 31;
            stg[c * ZSTR + lane] = a;          // stage[node][batch]
            if (c == 31) {
                __syncwarp();
                int g = ((i - HIDEND) >> 5) << 5;
                #pragma unroll 4
                for (int m = 0; m < 32; ++m) {
                    // lane -> output column (coalesced 128B), conflict-free LDS
                    out[(size_t)(b0 + m) * NOUT + g + lane] = stg[lane * ZSTR + m];
                }
                __syncwarp();
            }
        }
        sl = (sl + 1) & 3;
    }
}

// ============================================================================
extern "C" void kernel_launch(void* const* d_in, const int* in_sizes, int n_in,
                              void* d_out, int out_size)
{
    const float* x = nullptr;
    const float* W = nullptr;
    const float* b = nullptr;
    for (int i = 0; i < n_in; ++i) {
        if      (in_sizes[i] == BATCH * NIN)     x = (const float*)d_in[i];
        else if (in_sizes[i] == NNODES * NNODES) W = (const float*)d_in[i];
        else if (in_sizes[i] == NNODES)          b = (const float*)d_in[i];
    }

    build_csr_kernel<<<NNODES, 32>>>(W);

    int smem_bytes = (2 * HIDEND * ZSTR      // z
                    + 2 * 32 * ZSTR          // output staging
                    + 2 * 4 * MAXP * 2       // ring buffers
                    + NNODES) * (int)sizeof(float)
                    + NNODES * (int)sizeof(int);   // = 227,584 B
    cudaFuncSetAttribute(dagnn_main,
                         cudaFuncAttributeMaxDynamicSharedMemorySize, smem_bytes);

    dagnn_main<<<BATCH / 64, 64, smem_bytes>>>(x, b, (float*)d_out);
}

// round 4
// speedup vs baseline: 1.9524x; 1.9440x over previous
#include <cuda_runtime.h>
#include <cstdint>

#define NN     1024
#define NINP   256
#define NOUTP  256
#define NBAT   8192
#define MAXP   96     // extra-block pairs cap (max nnz/row ~60)
#define IMAX   12     // intra-block pairs cap (mean ~0.8, P(overflow) ~1e-10)
#define BS     32     // node block size
#define NBLK   24     // (512 hidden + 256 out) / 32
#define THREADS 256

__device__ int2 g_pairs[NN * MAXP];  // extra-block: {col*33, bits(w)}, ascending
__device__ int2 g_intra[NN * IMAX];  // intra-block, zero-padded
__device__ int2 g_meta [NN];         // {s1 = #extra pairs, bits(bias)}
__device__ int  g_icnt [NN];

// ============================================================================
// Build kernel: one warp per row; ascending col scan; ballot compaction.
// ============================================================================
__global__ void build_csr(const float* __restrict__ W, const float* __restrict__ b)
{
    int row = blockIdx.x, lane = threadIdx.x;
    int base = (row >= NINP && row < NN - NOUTP)
             ? (NINP + ((row - NINP) / BS) * BS) : NN;
    int s1 = 0, ic = 0;
    unsigned lt = (1u << lane) - 1u;
    for (int m = 0; m < 32; ++m) {
        int col = m * 32 + lane;
        float wv = W[(size_t)row * NN + col];
        bool nz = (wv != 0.0f);
        unsigned balE = __ballot_sync(~0u, nz && col <  base);
        unsigned balI = __ballot_sync(~0u, nz && col >= base);
        if (nz) {
            if (col < base) {
                int p = s1 + __popc(balE & lt);
                if (p < MAXP)
                    g_pairs[row * MAXP + p] = make_int2(col * 33, __float_as_int(wv));
            } else {
                int p = ic + __popc(balI & lt);
                if (p < IMAX)
                    g_intra[row * IMAX + p] = make_int2(col * 33, __float_as_int(wv));
            }
        }
        s1 += __popc(balE); ic += __popc(balI);
    }
    for (int t = ic + lane; t < IMAX; t += 32) g_intra[row * IMAX + t] = make_int2(0, 0);
    if (lane == 0) {
        g_meta[row] = make_int2((s1 < MAXP) ? s1 : MAXP, __float_as_int(b[row]));
        g_icnt[row] = (ic < IMAX) ? ic : IMAX;
    }
}

// ============================================================================
// Main kernel: CTA = 256 threads = 8 warps, 32 batch columns (lane = column).
// smem: z[768][33] | acc[32][33] | icnts[32] | ipb[32][IMAX]  = 108,800 B
// Per block k: Phase A (parallel, rows' extra-block dots) -> bar ->
//              Phase B (warp 7 serial intra solve + tanh) or writeout -> bar.
// ============================================================================
extern __shared__ float sm[];

__global__ void __launch_bounds__(THREADS, 2)
dagnn_main(const float* __restrict__ x, float* __restrict__ out)
{
    float* z     = sm;                         // 768*33 floats
    float* acc   = z + 768 * 33;               // 32*33 floats
    int*   icnts = (int*)(acc + 32 * 33);      // 32 ints
    int2*  ipb   = (int2*)(icnts + 32);        // 32*IMAX int2

    int tid = threadIdx.x, w = tid >> 5, lane = tid & 31;
    int b0 = blockIdx.x * 32;

    // fill z with inputs: coalesced LDG, conflict-free STS (stride 33)
    #pragma unroll
    for (int it = 0; it < 32; ++it) {
        int t = tid + it * THREADS;
        int n = t & 255, r = t >> 8;
        z[n * 33 + r] = x[(size_t)(b0 + r) * NINP + n];
    }
    __syncthreads();

    for (int k = 0; k < NBLK; ++k) {
        int base = NINP + k * BS;
        bool isHid = (k < 16);

        // cooperative stage of intra pairs + counts for this block
        if (isHid) {
            const int4* src = (const int4*)(g_intra + (size_t)base * IMAX);
            if (tid < (BS * IMAX) / 2) ((int4*)ipb)[tid] = __ldg(src + tid);
            if (tid >= 224) icnts[tid - 224] = g_icnt[base + tid - 224];
        }

        // Phase A: each warp computes 4 rows (w, w+8, w+16, w+24)
        #pragma unroll
        for (int j = 0; j < 4; ++j) {
            int n = w + 8 * j;
            int row = base + n;
            int2 mt = __ldg(&g_meta[row]);
            int s1 = mt.x;
            float a0 = __int_as_float(mt.y), a1 = 0.0f;
            const int4* p4 = (const int4*)(g_pairs + (size_t)row * MAXP);
            int h = s1 >> 1;
            #pragma unroll 8
            for (int q = 0; q < h; ++q) {
                int4 pp = __ldg(p4 + q);
                a0 = fmaf(__int_as_float(pp.y), z[pp.x + lane], a0);
                a1 = fmaf(__int_as_float(pp.w), z[pp.z + lane], a1);
            }
            if (s1 & 1) {
                int2 pp = __ldg(((const int2*)p4) + s1 - 1);
                a0 = fmaf(__int_as_float(pp.y), z[pp.x + lane], a0);
            }
            acc[n * 33 + lane] = a0 + a1;
        }
        __syncthreads();

        if (isHid) {
            if (w == 7) {   // serial intra-block solve + tanh
                for (int n = 0; n < BS; ++n) {
                    float a = acc[n * 33 + lane];
                    int ic = icnts[n];
                    const int2* q = ipb + n * IMAX;
                    for (int s = 0; s < ic; ++s) {
                        int2 pp = q[s];
                        a = fmaf(__int_as_float(pp.y), z[pp.x + lane], a);
                    }
                    float e = __expf(a + a);   // tanh, saturates at +/-inf
                    z[(base + n) * 33 + lane] = 1.0f - __fdividef(2.0f, e + 1.0f);
                }
            }
        } else {
            // output block: ALL 32 batch rows x 32 nodes (4 passes of 256 thr)
            int nn = tid & 31;
            #pragma unroll
            for (int r4 = 0; r4 < 4; ++r4) {
                int bb = (tid >> 5) + 8 * r4;
                out[(size_t)(b0 + bb) * NOUTP + (base - 768) + nn] = acc[nn * 33 + bb];
            }
        }
        __syncthreads();
    }
}

// ============================================================================
extern "C" void kernel_launch(void* const* d_in, const int* in_sizes, int n_in,
                              void* d_out, int out_size)
{
    const float* x = nullptr; const float* W = nullptr; const float* b = nullptr;
    for (int i = 0; i < n_in; ++i) {
        if      (in_sizes[i] == NBAT * NINP) x = (const float*)d_in[i];
        else if (in_sizes[i] == NN * NN)     W = (const float*)d_in[i];
        else if (in_sizes[i] == NN)          b = (const float*)d_in[i];
    }

    build_csr<<<NN, 32>>>(W, b);

    int smem_bytes = (768 * 33 + 32 * 33) * 4 + 32 * 4 + BS * IMAX * 8; // 108800
    cudaFuncSetAttribute(dagnn_main,
                         cudaFuncAttributeMaxDynamicSharedMemorySize, smem_bytes);
    dagnn_main<<<NBAT / 32, THREADS, smem_bytes>>>(x, (float*)d_out);
}

// round 6
// speedup vs baseline: 2.6248x; 1.3444x over previous
#include <cuda_runtime.h>
#include <cstdint>

#define NN     1024
#define NINP   256
#define NOUTP  256
#define NBAT   8192
#define MAXF   96     // far pairs cap per row (max ~68 stat, 9-sigma margin)
#define BPMAX  16     // near+intra pairs cap (mean ~3.2, P(>16) ~ 1e-9)
#define NBLK   24
#define THREADS 512   // 16 warps; 64 batch columns as float2 per lane

__device__ int2 g_pairs[NN * MAXF];  // far: {col*33 (float2 idx), bits(w)}
__device__ int2 g_bp   [NN * BPMAX]; // near+intra, zero-padded
__device__ int2 g_meta [NN];         // {far count, bits(bias)}
__device__ int  g_bcnt [NN];

// ============================================================================
// Build: one warp/row. far = col < blockbase-32 ; bp = col >= blockbase-32.
// ============================================================================
__global__ void build_csr(const float* __restrict__ W, const float* __restrict__ b)
{
    int row = blockIdx.x, lane = threadIdx.x;
    int fb = (row >= NINP) ? (NINP + (((row - NINP) >> 5) << 5) - 32) : 0;
    int fc = 0, bc = 0;
    unsigned lt = (1u << lane) - 1u;
    for (int m = 0; m < 32; ++m) {
        int col = m * 32 + lane;
        float wv = W[(size_t)row * NN + col];
        bool nz = (wv != 0.0f);
        unsigned bf = __ballot_sync(~0u, nz && col <  fb);
        unsigned bb = __ballot_sync(~0u, nz && col >= fb);
        if (nz) {
            if (col < fb) {
                int p = fc + __popc(bf & lt);
                if (p < MAXF) g_pairs[row*MAXF+p] = make_int2(col*33, __float_as_int(wv));
            } else {
                int p = bc + __popc(bb & lt);
                if (p < BPMAX) g_bp[row*BPMAX+p] = make_int2(col*33, __float_as_int(wv));
            }
        }
        fc += __popc(bf); bc += __popc(bb);
    }
    for (int t = bc + lane; t < BPMAX; t += 32) g_bp[row*BPMAX+t] = make_int2(0,0);
    if (lane == 0) {
        g_meta[row] = make_int2(fc < MAXF ? fc : MAXF, __float_as_int(b[row]));
        g_bcnt[row] = bc < BPMAX ? bc : BPMAX;
    }
}

// ============================================================================
// Main kernel. smem layout (bytes):
//   z2   [768][33] float2   @0        202752
//   accA [2][32*33] float   @202752     8448
//   accB [2][32*33] float   @211200     8448
//   bpb  [2][32*16] int2    @219648     8192
//   bcs  [2][32]    int     @227840      256   total 228096
// ============================================================================
extern __shared__ char smraw[];

__device__ __forceinline__ float tanhfast(float v) {
    float e = __expf(v + v);
    return 1.0f - __fdividef(2.0f, e + 1.0f);
}

__device__ __forceinline__ void afar_row(int row, int n, float* aA, float* aB,
                                         int lane, const float2* z2)
{
    int2 mt = __ldg(&g_meta[row]);
    int cnt = mt.x;
    float bias = __int_as_float(mt.y);
    float xA0 = bias, xB0 = bias, xA1 = 0.f, xB1 = 0.f;
    const int4* p4 = (const int4*)(g_pairs + (size_t)row * MAXF);
    int h = cnt >> 1;
    #pragma unroll 8
    for (int q = 0; q < h; ++q) {
        int4 pp = __ldg(p4 + q);
        float2 za = z2[pp.x + lane];
        float2 zb = z2[pp.z + lane];
        float w0 = __int_as_float(pp.y), w1 = __int_as_float(pp.w);
        xA0 = fmaf(w0, za.x, xA0); xB0 = fmaf(w0, za.y, xB0);
        xA1 = fmaf(w1, zb.x, xA1); xB1 = fmaf(w1, zb.y, xB1);
    }
    if (cnt & 1) {
        int2 pp = __ldg((const int2*)p4 + (cnt - 1));
        float2 za = z2[pp.x + lane];
        float w0 = __int_as_float(pp.y);
        xA0 = fmaf(w0, za.x, xA0); xB0 = fmaf(w0, za.y, xB0);
    }
    aA[n*33 + lane] = xA0 + xA1;
    aB[n*33 + lane] = xB0 + xB1;
}

__global__ void __launch_bounds__(THREADS, 1)
dagnn_main(const float* __restrict__ x, float* __restrict__ out)
{
    float2* z2   = (float2*)smraw;
    float*  accA = (float*)(smraw + 202752);
    float*  accB = (float*)(smraw + 211200);
    int2*   bpb  = (int2*) (smraw + 219648);
    int*    bcs  = (int*)  (smraw + 227840);

    int tid = threadIdx.x, w = tid >> 5, lane = tid & 31;
    int b0 = blockIdx.x * 64;
    float* zf = (float*)z2;

    // stage bp(0) early (independent LDGs)
    if (tid < 256)
        ((int4*)bpb)[tid] = __ldg((const int4*)(g_bp + (size_t)NINP * BPMAX) + tid);
    if (tid < 32) bcs[tid] = g_bcnt[NINP + tid];

    // transpose x into z2: float index n*66 + c  == z2[n*33 + c/2].(c&1)
    #pragma unroll
    for (int it = 0; it < 32; ++it) {
        int t = tid + it * THREADS;
        int n = t & 255, c = t >> 8;
        zf[n * 66 + c] = x[(size_t)(b0 + c) * NINP + n];
    }
    __syncthreads();

    // prologue: A_far(0) by all 16 warps (rows w, w+16)
    afar_row(NINP + w,      w,      accA, accB, lane, z2);
    afar_row(NINP + w + 16, w + 16, accA, accB, lane, z2);
    __syncthreads();

    for (int k = 0; k < NBLK; ++k) {
        int base = NINP + k * 32;
        int pk = k & 1, pn = pk ^ 1;

        if (w == 15) {
            // ---- prefetch bp(k+1) into regs (latency hidden under PhaseB) ---
            int4 st[8]; int cn = 0;
            bool more = (k + 1 < NBLK);
            if (more) {
                const int4* src = (const int4*)(g_bp + (size_t)(base + 32) * BPMAX);
                #pragma unroll
                for (int j = 0; j < 8; ++j) st[j] = __ldg(src + lane + 32 * j);
                cn = __ldg(&g_bcnt[base + 32 + lane]);
            }
            // ---- Phase B(k): near+intra pairs, then tanh / writeout --------
            float* aA = accA + pk * (32 * 33);
            float* aB = accB + pk * (32 * 33);
            const int2* bq = bpb + pk * (32 * BPMAX);
            const int*  bcn = bcs + pk * 32;
            if (k < 16) {
                for (int n = 0; n < 32; ++n) {
                    float vA = aA[n*33+lane], vB = aB[n*33+lane];
                    int c = bcn[n];
                    const int2* q = bq + n * BPMAX;
                    for (int s = 0; s < c; ++s) {
                        int2 p = q[s];
                        float2 zz = z2[p.x + lane];
                        float wv = __int_as_float(p.y);
                        vA = fmaf(wv, zz.x, vA); vB = fmaf(wv, zz.y, vB);
                    }
                    z2[(base + n) * 33 + lane] = make_float2(tanhfast(vA), tanhfast(vB));
                }
            } else {
                int goff = base - 768;
                for (int n = 0; n < 32; ++n) {
                    float vA = aA[n*33+lane], vB = aB[n*33+lane];
                    int c = bcn[n];
                    const int2* q = bq + n * BPMAX;
                    for (int s = 0; s < c; ++s) {
                        int2 p = q[s];
                        float2 zz = z2[p.x + lane];
                        float wv = __int_as_float(p.y);
                        vA = fmaf(wv, zz.x, vA); vB = fmaf(wv, zz.y, vB);
                    }
                    aA[n*33+lane] = vA; aB[n*33+lane] = vB;
                }
                __syncwarp();
                #pragma unroll 4
                for (int c2 = 0; c2 < 64; ++c2) {
                    float v = (c2 & 1) ? aB[lane*33 + (c2 >> 1)]
                                       : aA[lane*33 + (c2 >> 1)];
                    out[(size_t)(b0 + c2) * NOUTP + goff + lane] = v;
                }
            }
            // ---- commit staged bp(k+1) -------------------------------------
            if (more) {
                int4* dst = (int4*)(bpb + pn * (32 * BPMAX));
                #pragma unroll
                for (int j = 0; j < 8; ++j) dst[lane + 32 * j] = st[j];
                bcs[pn * 32 + lane] = cn;
            }
        } else if (k + 1 < NBLK) {
            // ---- Phase A_far(k+1) on warps 0..14 ---------------------------
            int kb = k + 1;
            float* aA = accA + (kb & 1) * (32 * 33);
            float* aB = accB + (kb & 1) * (32 * 33);
            int nb = NINP + kb * 32;
            afar_row(nb + w,      w,      aA, aB, lane, z2);
            afar_row(nb + w + 15, w + 15, aA, aB, lane, z2);
            if (w < 2)
                afar_row(nb + w + 30, w + 30, aA, aB, lane, z2);
        }
        __syncthreads();
    }
}

// ============================================================================
extern "C" void kernel_launch(void* const* d_in, const int* in_sizes, int n_in,
                              void* d_out, int out_size)
{
    const float* x = nullptr; const float* W = nullptr; const float* b = nullptr;
    for (int i = 0; i < n_in; ++i) {
        if      (in_sizes[i] == NBAT * NINP) x = (const float*)d_in[i];
        else if (in_sizes[i] == NN * NN)     W = (const float*)d_in[i];
        else if (in_sizes[i] == NN)          b = (const float*)d_in[i];
    }

    build_csr<<<NN, 32>>>(W, b);

    int smem_bytes = 228096;
    cudaFuncSetAttribute(dagnn_main,
                         cudaFuncAttributeMaxDynamicSharedMemorySize, smem_bytes);
    dagnn_main<<<NBAT / 64, THREADS, smem_bytes>>>(x, (float*)d_out);
}

// round 7
// speedup vs baseline: 3.0650x; 1.1677x over previous
#include <cuda_runtime.h>
#include <cstdint>

#define NN     1024
#define NINP   256
#define NOUTP  256
#define NBAT   8192
#define MAXF   96     // far pairs cap per row (max ~68 stat)
#define IMAX   16     // intra-block pairs cap (proven sufficient in prior rounds)
#define THREADS 512   // 16 warps; 64 batch columns (float2 per lane)

__device__ int2 g_pairs[NN * MAXF];   // far: {col*33 (float2 idx), bits(w)}
__device__ int2 g_intra[NN * IMAX];   // intra-block pairs (hidden rows only)
__device__ int2 g_meta [NN];          // {far count, bits(bias)}
__device__ int  g_icnt [NN];
__device__ int  g_ordic[16 * 32];     // per block: node | (icnt<<8), level-sorted
__device__ int  g_lst  [16 * 34];     // per block: level start offsets (end=32)

// ============================================================================
// Build 1: per-row split into far (col < own block base; outputs: everything)
// and intra (col >= block base). One warp per row, ascending-col ballots.
// ============================================================================
__global__ void build_csr(const float* __restrict__ W, const float* __restrict__ b)
{
    int row = blockIdx.x, lane = threadIdx.x;
    int fb;
    if (row < NINP)            fb = 0;
    else if (row < NN - NOUTP) fb = NINP + (((row - NINP) >> 5) << 5);
    else                       fb = NN;
    int fc = 0, ic = 0;
    unsigned lt = (1u << lane) - 1u;
    for (int m = 0; m < 32; ++m) {
        int col = m * 32 + lane;
        float wv = W[(size_t)row * NN + col];
        bool nz = (wv != 0.0f);
        unsigned bf = __ballot_sync(~0u, nz && col <  fb);
        unsigned bi = __ballot_sync(~0u, nz && col >= fb);
        if (nz) {
            if (col < fb) {
                int p = fc + __popc(bf & lt);
                if (p < MAXF) g_pairs[row*MAXF+p] = make_int2(col*33, __float_as_int(wv));
            } else {
                int p = ic + __popc(bi & lt);
                if (p < IMAX) g_intra[row*IMAX+p] = make_int2(col*33, __float_as_int(wv));
            }
        }
        fc += __popc(bf); ic += __popc(bi);
    }
    for (int t = ic + lane; t < IMAX; t += 32) g_intra[row*IMAX+t] = make_int2(0,0);
    if (lane == 0) {
        g_meta[row] = make_int2(fc < MAXF ? fc : MAXF, __float_as_int(b[row]));
        g_icnt[row] = ic < IMAX ? ic : IMAX;
    }
}

// ============================================================================
// Build 2: per hidden block, compute dependency levels of the 32 nodes and a
// level-sorted order. One warp per block.
// ============================================================================
__global__ void build_levels()
{
    int blk = blockIdx.x, n = threadIdx.x;     // node within block
    int base = NINP + blk * 32;
    int row = base + n;
    int ic = g_icnt[row];
    unsigned mymask = 0;
    for (int s = 0; s < ic; ++s) {
        int d = g_intra[row * IMAX + s].x / 33 - base;   // in-block source idx
        mymask |= 1u << d;
    }
    int lvl = -1;
    unsigned done = 0;
    for (int it = 0; it < 32; ++it) {
        bool rdy = (lvl < 0) && ((mymask & ~done) == 0);
        unsigned bal = __ballot_sync(~0u, rdy);
        if (rdy) lvl = it;
        done |= bal;
        if (done == 0xffffffffu) break;
    }
    unsigned lt = (1u << n) - 1u;
    int run = 0, pos = 0;
    for (int L = 0; L < 32; ++L) {
        unsigned bal = __ballot_sync(~0u, lvl == L);
        if (lvl == L) pos = run + __popc(bal & lt);
        if (n == 0 && L < 34) g_lst[blk * 34 + L] = (run < 32) ? run : 32;
        run += __popc(bal);
    }
    if (n < 2) g_lst[blk * 34 + 32 + n] = 32;   // sentinel tail
    g_ordic[blk * 32 + pos] = n | (ic << 8);
}

// ============================================================================
// Main kernel. smem (bytes):
//   z2   [768][33] float2 @0       202752
//   accA [32*33] f        @202752    4224
//   accB [32*33] f        @206976    4224
//   ipb  [32*16] int2     @211200    4096
//   sord [32] int         @215296     128
//   slst [34] int         @215424     136   total 215560
// ============================================================================
extern __shared__ char smraw[];

__device__ __forceinline__ float tanhfast(float v) {
    float e = __expf(v + v);
    return 1.0f - __fdividef(2.0f, e + 1.0f);
}

__device__ __forceinline__ void afar_row(int row, int n, float* aA, float* aB,
                                         int lane, const float2* z2)
{
    int2 mt = __ldg(&g_meta[row]);
    int cnt = mt.x;
    float bias = __int_as_float(mt.y);
    float xA0 = bias, xB0 = bias, xA1 = 0.f, xB1 = 0.f;
    const int4* p4 = (const int4*)(g_pairs + (size_t)row * MAXF);
    int h = cnt >> 1;
    #pragma unroll 8
    for (int q = 0; q < h; ++q) {
        int4 pp = __ldg(p4 + q);
        float2 za = z2[pp.x + lane];
        float2 zb = z2[pp.z + lane];
        float w0 = __int_as_float(pp.y), w1 = __int_as_float(pp.w);
        xA0 = fmaf(w0, za.x, xA0); xB0 = fmaf(w0, za.y, xB0);
        xA1 = fmaf(w1, zb.x, xA1); xB1 = fmaf(w1, zb.y, xB1);
    }
    if (cnt & 1) {
        int2 pp = __ldg((const int2*)p4 + (cnt - 1));
        float2 za = z2[pp.x + lane];
        float w0 = __int_as_float(pp.y);
        xA0 = fmaf(w0, za.x, xA0); xB0 = fmaf(w0, za.y, xB0);
    }
    aA[n*33 + lane] = xA0 + xA1;
    aB[n*33 + lane] = xB0 + xB1;
}

__global__ void __launch_bounds__(THREADS, 1)
dagnn_main(const float* __restrict__ x, float* __restrict__ out)
{
    float2* z2   = (float2*)smraw;
    float*  accA = (float*)(smraw + 202752);
    float*  accB = (float*)(smraw + 206976);
    int2*   ipb  = (int2*) (smraw + 211200);
    int*    sord = (int*)  (smraw + 215296);
    int*    slst = (int*)  (smraw + 215424);

    int tid = threadIdx.x, w = tid >> 5, lane = tid & 31;
    int b0 = blockIdx.x * 64;
    float* zf = (float*)z2;

    // transpose x into z2
    #pragma unroll
    for (int it = 0; it < 32; ++it) {
        int t = tid + it * THREADS;
        int n = t & 255, c = t >> 8;
        zf[n * 66 + c] = x[(size_t)(b0 + c) * NINP + n];
    }
    __syncthreads();

    // ---------------- hidden blocks ----------------
    for (int k = 0; k < 16; ++k) {
        int base = NINP + k * 32;

        // stage intra pairs + order + level starts (cooperative, pre-barrier)
        if (tid < 256)
            ((int4*)ipb)[tid] = __ldg((const int4*)(g_intra + (size_t)base * IMAX) + tid);
        else if (tid < 288)
            sord[tid - 256] = __ldg(&g_ordic[k * 32 + tid - 256]);
        else if (tid < 322)
            slst[tid - 288] = __ldg(&g_lst[k * 34 + tid - 288]);

        // far phase: all 16 warps, rows (w, w+16)
        afar_row(base + w,      w,      accA, accB, lane, z2);
        afar_row(base + w + 16, w + 16, accA, accB, lane, z2);
        __syncthreads();

        // level-parallel intra + tanh
        for (int L = 0; slst[L] < 32; ++L) {
            for (int j = slst[L] + w; j < slst[L + 1]; j += 16) {
                int oi = sord[j];
                int n  = oi & 255;
                int ic = oi >> 8;
                float vA = accA[n*33 + lane], vB = accB[n*33 + lane];
                const int2* q = ipb + n * IMAX;
                for (int s = 0; s < ic; ++s) {
                    int2 p = q[s];
                    float2 zz = z2[p.x + lane];
                    float wv = __int_as_float(p.y);
                    vA = fmaf(wv, zz.x, vA); vB = fmaf(wv, zz.y, vB);
                }
                z2[(base + n) * 33 + lane] = make_float2(tanhfast(vA), tanhfast(vB));
            }
            __syncthreads();
        }
        __syncthreads();   // ensure last level visible before next far phase
    }

    // ---------------- output epilogue: 8 chunks, fully parallel ----------------
    for (int ko = 0; ko < 8; ++ko) {
        int base = NN - NOUTP + ko * 32;
        afar_row(base + w,      w,      accA, accB, lane, z2);
        afar_row(base + w + 16, w + 16, accA, accB, lane, z2);
        __syncthreads();
        int goff = base - (NN - NOUTP);
        #pragma unroll
        for (int rr = 0; rr < 4; ++rr) {
            int c2 = (tid >> 5) + 16 * rr;
            int j  = c2 >> 1;
            float v = (c2 & 1) ? accB[lane*33 + j] : accA[lane*33 + j];
            out[(size_t)(b0 + c2) * NOUTP + goff + lane] = v;
        }
        __syncthreads();
    }
}

// ============================================================================
extern "C" void kernel_launch(void* const* d_in, const int* in_sizes, int n_in,
                              void* d_out, int out_size)
{
    const float* x = nullptr; const float* W = nullptr; const float* b = nullptr;
    for (int i = 0; i < n_in; ++i) {
        if      (in_sizes[i] == NBAT * NINP) x = (const float*)d_in[i];
        else if (in_sizes[i] == NN * NN)     W = (const float*)d_in[i];
        else if (in_sizes[i] == NN)          b = (const float*)d_in[i];
    }

    build_csr<<<NN, 32>>>(W, b);
    build_levels<<<16, 32>>>();

    int smem_bytes = 215560;
    cudaFuncSetAttribute(dagnn_main,
                         cudaFuncAttributeMaxDynamicSharedMemorySize, smem_bytes);
    dagnn_main<<<NBAT / 64, THREADS, smem_bytes>>>(x, (float*)d_out);
}